// round 1
// baseline (speedup 1.0000x reference)
#include <cuda_runtime.h>
#include <math.h>

#define NL  8
#define D   1024
#define NH  16
#define VOC 32000
#define TT  1024
#define BB  2
#define HDIM 64
#define MM  2048   // B*T

// ---------------- scratch (device globals; no allocations allowed) ----------
static __device__ float g_X  [(size_t)MM * D];
static __device__ float g_Hb [(size_t)MM * D];
static __device__ float g_QKV[(size_t)MM * 3 * D];
static __device__ float g_S  [(size_t)BB * NH * TT * TT];   // 128 MB attn scores
static __device__ float g_Y  [(size_t)MM * D];
static __device__ float g_FF [(size_t)MM * 4 * D];
static __device__ float g_NLL[(size_t)MM];

// ---------------- block reductions ------------------------------------------
__device__ __forceinline__ float blk_sum(float v, float* sh) {
    #pragma unroll
    for (int o = 16; o; o >>= 1) v += __shfl_xor_sync(0xffffffffu, v, o);
    if ((threadIdx.x & 31) == 0) sh[threadIdx.x >> 5] = v;
    __syncthreads();
    float r = 0.f;
    #pragma unroll
    for (int i = 0; i < 8; i++) r += sh[i];
    __syncthreads();
    return r;
}

__device__ __forceinline__ float blk_max(float v, float* sh) {
    #pragma unroll
    for (int o = 16; o; o >>= 1) v = fmaxf(v, __shfl_xor_sync(0xffffffffu, v, o));
    if ((threadIdx.x & 31) == 0) sh[threadIdx.x >> 5] = v;
    __syncthreads();
    float r = -1e30f;
    #pragma unroll
    for (int i = 0; i < 8; i++) r = fmaxf(r, sh[i]);
    __syncthreads();
    return r;
}

// ---------------- embedding --------------------------------------------------
__global__ void embed_k(const int* __restrict__ idx, const float* __restrict__ tok,
                        const float* __restrict__ pos, float* __restrict__ X) {
    const int r = blockIdx.x;          // 0..MM-1  (b*T + t)
    const int t = r & (TT - 1);
    const int id = idx[r];
    const float* te = tok + (size_t)id * D;
    const float* pe = pos + (size_t)t * D;
    float* xr = X + (size_t)r * D;
    for (int c = threadIdx.x; c < D; c += 256)
        xr[c] = te[c] + pe[c];
}

// ---------------- layernorm (256 threads, 4 elems each) ----------------------
__global__ void __launch_bounds__(256) ln_k(const float* __restrict__ X,
                                            const float* __restrict__ s,
                                            const float* __restrict__ b,
                                            float* __restrict__ O) {
    __shared__ float sh[8];
    const int r = blockIdx.x;
    const float* xr = X + (size_t)r * D;
    const int base = threadIdx.x << 2;
    float4 xv = *(const float4*)(xr + base);
    float sum = xv.x + xv.y + xv.z + xv.w;
    float mean = blk_sum(sum, sh) * (1.f / D);
    float dx = xv.x - mean, dy = xv.y - mean, dz = xv.z - mean, dw = xv.w - mean;
    float var = blk_sum(dx*dx + dy*dy + dz*dz + dw*dw, sh) * (1.f / D);
    float rinv = rsqrtf(var + 1e-5f);
    float4 sv = *(const float4*)(s + base);
    float4 bv = *(const float4*)(b + base);
    float4 o;
    o.x = dx * rinv * sv.x + bv.x;
    o.y = dy * rinv * sv.y + bv.y;
    o.z = dz * rinv * sv.z + bv.z;
    o.w = dw * rinv * sv.w + bv.w;
    *(float4*)(O + (size_t)r * D + base) = o;
}

// ---------------- GEMM: C = epi(A[M,K] @ W[K,N] + bias (+res)) ---------------
// 128x128 tile, BK=16, 256 threads, 8x8 per-thread register tile.
template<int DO_BIAS, int DO_GELU, int DO_RES>
__global__ void __launch_bounds__(256) gemm_k(
    const float* __restrict__ A, const float* __restrict__ W,
    const float* __restrict__ bias, const float* res,
    float* C, int M, int N, int K)
{
    __shared__ float As[16][132];   // padded, stored transposed [k][m]
    __shared__ float Bs[16][128];
    const int bm = blockIdx.y << 7;
    const int bn = blockIdx.x << 7;
    const int tid = threadIdx.x;
    const int tx = tid & 15;
    const int ty = tid >> 4;

    float acc[8][8];
    #pragma unroll
    for (int i = 0; i < 8; i++)
        #pragma unroll
        for (int j = 0; j < 8; j++) acc[i][j] = 0.f;

    for (int k0 = 0; k0 < K; k0 += 16) {
        #pragma unroll
        for (int i = 0; i < 2; i++) {
            const int idx = tid + (i << 8);         // 0..511
            const int ar = idx >> 2;                // 0..127
            const int ac = (idx & 3) << 2;          // 0,4,8,12
            const float4 av = *(const float4*)&A[(size_t)(bm + ar) * K + k0 + ac];
            As[ac + 0][ar] = av.x; As[ac + 1][ar] = av.y;
            As[ac + 2][ar] = av.z; As[ac + 3][ar] = av.w;
            const int br = idx >> 5;                // 0..15
            const int bc = (idx & 31) << 2;         // 0..124
            *(float4*)&Bs[br][bc] = *(const float4*)&W[(size_t)(k0 + br) * N + bn + bc];
        }
        __syncthreads();
        #pragma unroll
        for (int kk = 0; kk < 16; kk++) {
            float a[8], b[8];
            *(float4*)(a)     = *(const float4*)&As[kk][ty << 3];
            *(float4*)(a + 4) = *(const float4*)&As[kk][(ty << 3) + 4];
            *(float4*)(b)     = *(const float4*)&Bs[kk][tx << 3];
            *(float4*)(b + 4) = *(const float4*)&Bs[kk][(tx << 3) + 4];
            #pragma unroll
            for (int i = 0; i < 8; i++)
                #pragma unroll
                for (int j = 0; j < 8; j++)
                    acc[i][j] = fmaf(a[i], b[j], acc[i][j]);
        }
        __syncthreads();
    }

    float bv[8];
    #pragma unroll
    for (int j = 0; j < 8; j++) bv[j] = DO_BIAS ? bias[bn + (tx << 3) + j] : 0.f;

    #pragma unroll
    for (int i = 0; i < 8; i++) {
        const int row = bm + (ty << 3) + i;
        const size_t off = (size_t)row * N + bn + (tx << 3);
        float v[8];
        #pragma unroll
        for (int j = 0; j < 8; j++) {
            float x = acc[i][j] + bv[j];
            if (DO_GELU) x = 0.5f * x * (1.f + erff(x * 0.70710678118f));
            v[j] = x;
        }
        if (DO_RES) {
            const float4 r0 = *(const float4*)(res + off);
            const float4 r1 = *(const float4*)(res + off + 4);
            v[0] += r0.x; v[1] += r0.y; v[2] += r0.z; v[3] += r0.w;
            v[4] += r1.x; v[5] += r1.y; v[6] += r1.z; v[7] += r1.w;
        }
        *(float4*)(C + off)     = make_float4(v[0], v[1], v[2], v[3]);
        *(float4*)(C + off + 4) = make_float4(v[4], v[5], v[6], v[7]);
    }
}

// ---------------- attention: scores = scale * Q @ K^T ------------------------
// grid: (T/64, T/64, B*H), 64x64 output tile, 4x4 per thread, K-dim = 64.
__global__ void __launch_bounds__(256) attn_scores_k(const float* __restrict__ QKV,
                                                     float* __restrict__ S) {
    __shared__ float Qs[64][68];   // [d][qrow]
    __shared__ float Ks[64][68];   // [d][krow]
    const int q0 = blockIdx.x << 6;
    const int k0 = blockIdx.y << 6;
    const int bh = blockIdx.z;
    const int b = bh >> 4, h = bh & 15;
    const int tid = threadIdx.x;
    #pragma unroll
    for (int i = 0; i < 4; i++) {
        const int idx = tid + (i << 8);
        const int row = idx >> 4;
        const int c4 = (idx & 15) << 2;
        const float4 qv = *(const float4*)&QKV[(size_t)(b * TT + q0 + row) * (3 * D) + h * HDIM + c4];
        Qs[c4 + 0][row] = qv.x; Qs[c4 + 1][row] = qv.y;
        Qs[c4 + 2][row] = qv.z; Qs[c4 + 3][row] = qv.w;
        const float4 kv = *(const float4*)&QKV[(size_t)(b * TT + k0 + row) * (3 * D) + D + h * HDIM + c4];
        Ks[c4 + 0][row] = kv.x; Ks[c4 + 1][row] = kv.y;
        Ks[c4 + 2][row] = kv.z; Ks[c4 + 3][row] = kv.w;
    }
    __syncthreads();
    const int tx = tid & 15, ty = tid >> 4;
    float acc[4][4];
    #pragma unroll
    for (int i = 0; i < 4; i++)
        #pragma unroll
        for (int j = 0; j < 4; j++) acc[i][j] = 0.f;
    #pragma unroll 8
    for (int d = 0; d < 64; d++) {
        float a[4], bb[4];
        *(float4*)a  = *(const float4*)&Qs[d][ty << 2];
        *(float4*)bb = *(const float4*)&Ks[d][tx << 2];
        #pragma unroll
        for (int i = 0; i < 4; i++)
            #pragma unroll
            for (int j = 0; j < 4; j++)
                acc[i][j] = fmaf(a[i], bb[j], acc[i][j]);
    }
    #pragma unroll
    for (int i = 0; i < 4; i++) {
        float* srow = &S[((size_t)bh * TT + q0 + (ty << 2) + i) * TT + k0 + (tx << 2)];
        *(float4*)srow = make_float4(acc[i][0] * 0.125f, acc[i][1] * 0.125f,
                                     acc[i][2] * 0.125f, acc[i][3] * 0.125f);
    }
}

// ---------------- softmax over key axis (one row per block) ------------------
__global__ void __launch_bounds__(256) softmax_k(float* __restrict__ S) {
    __shared__ float sh[8];
    float* row = S + (size_t)blockIdx.x * TT;
    const int base = threadIdx.x << 2;
    float4 v = *(const float4*)(row + base);
    float m = fmaxf(fmaxf(v.x, v.y), fmaxf(v.z, v.w));
    m = blk_max(m, sh);
    v.x = __expf(v.x - m); v.y = __expf(v.y - m);
    v.z = __expf(v.z - m); v.w = __expf(v.w - m);
    float s = blk_sum(v.x + v.y + v.z + v.w, sh);
    const float inv = 1.f / s;
    v.x *= inv; v.y *= inv; v.z *= inv; v.w *= inv;
    *(float4*)(row + base) = v;
}

// ---------------- attention: Y = P @ V ---------------------------------------
// grid: (T/64, B*H). Output [64 q-rows x 64 head-dims], 4x4 per thread.
__global__ void __launch_bounds__(256) attn_av_k(const float* __restrict__ S,
                                                 const float* __restrict__ QKV,
                                                 float* __restrict__ Y) {
    __shared__ float Ps[64][68];   // [k][qrow]
    __shared__ float Vs[64][68];   // [k][d]
    const int q0 = blockIdx.x << 6;
    const int bh = blockIdx.y;
    const int b = bh >> 4, h = bh & 15;
    const int tid = threadIdx.x;
    const int tx = tid & 15, ty = tid >> 4;
    float acc[4][4];
    #pragma unroll
    for (int i = 0; i < 4; i++)
        #pragma unroll
        for (int j = 0; j < 4; j++) acc[i][j] = 0.f;

    for (int kb = 0; kb < TT; kb += 64) {
        #pragma unroll
        for (int i = 0; i < 4; i++) {
            const int idx = tid + (i << 8);
            const int r = idx >> 4;
            const int c4 = (idx & 15) << 2;
            const float4 pv = *(const float4*)&S[((size_t)bh * TT + q0 + r) * TT + kb + c4];
            Ps[c4 + 0][r] = pv.x; Ps[c4 + 1][r] = pv.y;
            Ps[c4 + 2][r] = pv.z; Ps[c4 + 3][r] = pv.w;
            *(float4*)&Vs[r][c4] =
                *(const float4*)&QKV[(size_t)(b * TT + kb + r) * (3 * D) + 2 * D + h * HDIM + c4];
        }
        __syncthreads();
        #pragma unroll 8
        for (int kk = 0; kk < 64; kk++) {
            float a[4], bb[4];
            *(float4*)a  = *(const float4*)&Ps[kk][ty << 2];
            *(float4*)bb = *(const float4*)&Vs[kk][tx << 2];
            #pragma unroll
            for (int i = 0; i < 4; i++)
                #pragma unroll
                for (int j = 0; j < 4; j++)
                    acc[i][j] = fmaf(a[i], bb[j], acc[i][j]);
        }
        __syncthreads();
    }
    #pragma unroll
    for (int i = 0; i < 4; i++) {
        float* yrow = &Y[(size_t)(b * TT + q0 + (ty << 2) + i) * D + h * HDIM + (tx << 2)];
        *(float4*)yrow = make_float4(acc[i][0], acc[i][1], acc[i][2], acc[i][3]);
    }
}

// ---------------- loss -------------------------------------------------------
__global__ void __launch_bounds__(256) nll_k(const float* __restrict__ logits,
                                             const int* __restrict__ tgt,
                                             float* __restrict__ nll) {
    __shared__ float sh[8];
    const int r = blockIdx.x;
    const float* row = logits + (size_t)r * VOC;
    float m = -1e30f;
    for (int c = threadIdx.x; c < VOC; c += 256) m = fmaxf(m, row[c]);
    m = blk_max(m, sh);
    float s = 0.f;
    for (int c = threadIdx.x; c < VOC; c += 256) s += __expf(row[c] - m);
    s = blk_sum(s, sh);
    if (threadIdx.x == 0) nll[r] = m + logf(s) - row[tgt[r]];
}

__global__ void __launch_bounds__(256) loss_k(const float* __restrict__ nll,
                                              float* __restrict__ out) {
    __shared__ float sh[8];
    float s = 0.f;
    for (int i = threadIdx.x; i < MM; i += 256) s += nll[i];
    s = blk_sum(s, sh);
    if (threadIdx.x == 0) out[0] = s * (1.f / MM);
}

// ---------------- orchestration ----------------------------------------------
extern "C" void kernel_launch(void* const* d_in, const int* in_sizes, int n_in,
                              void* d_out, int out_size) {
    const int*   idx     = (const int*)  d_in[0];
    const int*   targets = (const int*)  d_in[1];
    const float* tok_emb = (const float*)d_in[2];
    const float* pos_emb = (const float*)d_in[3];
    const float* ln1_s   = (const float*)d_in[4];
    const float* ln1_b   = (const float*)d_in[5];
    const float* qkv_w   = (const float*)d_in[6];
    const float* qkv_b   = (const float*)d_in[7];
    const float* proj_w  = (const float*)d_in[8];
    const float* proj_b  = (const float*)d_in[9];
    const float* ln2_s   = (const float*)d_in[10];
    const float* ln2_b   = (const float*)d_in[11];
    const float* fc1_w   = (const float*)d_in[12];
    const float* fc1_b   = (const float*)d_in[13];
    const float* fc2_w   = (const float*)d_in[14];
    const float* fc2_b   = (const float*)d_in[15];
    const float* lnf_s   = (const float*)d_in[16];
    const float* lnf_b   = (const float*)d_in[17];
    const float* head_w  = (const float*)d_in[18];
    float* out = (float*)d_out;

    float *X, *Hb, *QKV, *S, *Y, *FF, *NLL;
    cudaGetSymbolAddress((void**)&X,   g_X);
    cudaGetSymbolAddress((void**)&Hb,  g_Hb);
    cudaGetSymbolAddress((void**)&QKV, g_QKV);
    cudaGetSymbolAddress((void**)&S,   g_S);
    cudaGetSymbolAddress((void**)&Y,   g_Y);
    cudaGetSymbolAddress((void**)&FF,  g_FF);
    cudaGetSymbolAddress((void**)&NLL, g_NLL);

    embed_k<<<MM, 256>>>(idx, tok_emb, pos_emb, X);

    for (int l = 0; l < NL; l++) {
        ln_k<<<MM, 256>>>(X, ln1_s + (size_t)l * D, ln1_b + (size_t)l * D, Hb);
        gemm_k<1,0,0><<<dim3(3 * D / 128, MM / 128), 256>>>(
            Hb, qkv_w + (size_t)l * D * 3 * D, qkv_b + (size_t)l * 3 * D,
            nullptr, QKV, MM, 3 * D, D);
        attn_scores_k<<<dim3(TT / 64, TT / 64, BB * NH), 256>>>(QKV, S);
        softmax_k<<<BB * NH * TT, 256>>>(S);
        attn_av_k<<<dim3(TT / 64, BB * NH), 256>>>(S, QKV, Y);
        gemm_k<1,0,1><<<dim3(D / 128, MM / 128), 256>>>(
            Y, proj_w + (size_t)l * D * D, proj_b + (size_t)l * D,
            X, X, MM, D, D);
        ln_k<<<MM, 256>>>(X, ln2_s + (size_t)l * D, ln2_b + (size_t)l * D, Hb);
        gemm_k<1,1,0><<<dim3(4 * D / 128, MM / 128), 256>>>(
            Hb, fc1_w + (size_t)l * D * 4 * D, fc1_b + (size_t)l * 4 * D,
            nullptr, FF, MM, 4 * D, D);
        gemm_k<1,0,1><<<dim3(D / 128, MM / 128), 256>>>(
            FF, fc2_w + (size_t)l * 4 * D * D, fc2_b + (size_t)l * D,
            X, X, MM, D, 4 * D);
    }

    ln_k<<<MM, 256>>>(X, lnf_s, lnf_b, Hb);
    gemm_k<0,0,0><<<dim3(VOC / 128, MM / 128), 256>>>(
        Hb, head_w, nullptr, nullptr, out, MM, VOC, D);

    nll_k<<<MM, 256>>>(out, targets, NLL);
    loss_k<<<1, 256>>>(NLL, out + (size_t)out_size - 1);
}

// round 2
// speedup vs baseline: 2.2621x; 2.2621x over previous
#include <cuda_runtime.h>
#include <math.h>
#include <stdint.h>

#define NL  8
#define D   1024
#define NH  16
#define VOC 32000
#define TT  1024
#define BB  2
#define HDIM 64
#define MM  2048   // B*T

// ---------------- scratch (device globals; no allocations allowed) ----------
static __device__ float g_X  [(size_t)MM * D];
static __device__ float g_Hb [(size_t)MM * D];
static __device__ float g_QKV[(size_t)MM * 3 * D];
static __device__ float g_S  [(size_t)BB * NH * TT * TT];   // 128 MB attn scores
static __device__ float g_Y  [(size_t)MM * D];
static __device__ float g_FF [(size_t)MM * 4 * D];
static __device__ float g_NLL[(size_t)MM];

// ---------------- helpers -----------------------------------------------------
__device__ __forceinline__ uint32_t f2tf(float f) {
    uint32_t r;
    asm("cvt.rna.tf32.f32 %0, %1;" : "=r"(r) : "f"(f));
    return r;
}

__device__ __forceinline__ float blk_sum(float v, float* sh) {
    #pragma unroll
    for (int o = 16; o; o >>= 1) v += __shfl_xor_sync(0xffffffffu, v, o);
    if ((threadIdx.x & 31) == 0) sh[threadIdx.x >> 5] = v;
    __syncthreads();
    float r = 0.f;
    #pragma unroll
    for (int i = 0; i < 8; i++) r += sh[i];
    __syncthreads();
    return r;
}

__device__ __forceinline__ float blk_max(float v, float* sh) {
    #pragma unroll
    for (int o = 16; o; o >>= 1) v = fmaxf(v, __shfl_xor_sync(0xffffffffu, v, o));
    if ((threadIdx.x & 31) == 0) sh[threadIdx.x >> 5] = v;
    __syncthreads();
    float r = -1e30f;
    #pragma unroll
    for (int i = 0; i < 8; i++) r = fmaxf(r, sh[i]);
    __syncthreads();
    return r;
}

// ---------------- embedding --------------------------------------------------
__global__ void embed_k(const int* __restrict__ idx, const float* __restrict__ tok,
                        const float* __restrict__ pos, float* __restrict__ X) {
    const int r = blockIdx.x;
    const int t = r & (TT - 1);
    const int id = idx[r];
    const float* te = tok + (size_t)id * D;
    const float* pe = pos + (size_t)t * D;
    float* xr = X + (size_t)r * D;
    for (int c = threadIdx.x; c < D; c += 256)
        xr[c] = te[c] + pe[c];
}

// ---------------- layernorm ---------------------------------------------------
__global__ void __launch_bounds__(256) ln_k(const float* __restrict__ X,
                                            const float* __restrict__ s,
                                            const float* __restrict__ b,
                                            float* __restrict__ O) {
    __shared__ float sh[8];
    const int r = blockIdx.x;
    const float* xr = X + (size_t)r * D;
    const int base = threadIdx.x << 2;
    float4 xv = *(const float4*)(xr + base);
    float sum = xv.x + xv.y + xv.z + xv.w;
    float mean = blk_sum(sum, sh) * (1.f / D);
    float dx = xv.x - mean, dy = xv.y - mean, dz = xv.z - mean, dw = xv.w - mean;
    float var = blk_sum(dx*dx + dy*dy + dz*dz + dw*dw, sh) * (1.f / D);
    float rinv = rsqrtf(var + 1e-5f);
    float4 sv = *(const float4*)(s + base);
    float4 bv = *(const float4*)(b + base);
    float4 o;
    o.x = dx * rinv * sv.x + bv.x;
    o.y = dy * rinv * sv.y + bv.y;
    o.z = dz * rinv * sv.z + bv.z;
    o.w = dw * rinv * sv.w + bv.w;
    *(float4*)(O + (size_t)r * D + base) = o;
}

// ---------------- TF32 tensor-core GEMM ---------------------------------------
// C[M,N] = epi(A[M,K] @ W[K,N] + bias (+res)).  128x128 tile, BK=16,
// 256 threads = 8 warps (2x4), warp tile 64x32, mma.m16n8k8.tf32.
#define MMA_TF32(d, a, b)                                                        \
    asm volatile(                                                                \
        "mma.sync.aligned.m16n8k8.row.col.f32.tf32.tf32.f32 "                    \
        "{%0,%1,%2,%3},{%4,%5,%6,%7},{%8,%9},{%0,%1,%2,%3};\n"                   \
        : "+f"(d[0]), "+f"(d[1]), "+f"(d[2]), "+f"(d[3])                         \
        : "r"(a[0]), "r"(a[1]), "r"(a[2]), "r"(a[3]), "r"(b[0]), "r"(b[1]))

template<int DO_BIAS, int DO_GELU, int DO_RES>
__global__ void __launch_bounds__(256) gemm_tf32_k(
    const float* __restrict__ A, const float* __restrict__ W,
    const float* __restrict__ bias, const float* __restrict__ res,
    float* __restrict__ C, int M, int N, int K)
{
    __shared__ uint32_t As[128][20];   // [m][k] pad->20: conflict-free frag loads
    __shared__ uint32_t Bs[16][136];   // [k][n] pad->136: conflict-free frag loads
    const int bm = blockIdx.y << 7;
    const int bn = blockIdx.x << 7;
    const int tid = threadIdx.x;
    const int warp = tid >> 5, lane = tid & 31;
    const int g = lane >> 2, t4 = lane & 3;
    const int wm = (warp >> 2) << 6;   // 0 or 64
    const int wn = (warp & 3) << 5;    // 0,32,64,96

    float acc[4][4][4];
    #pragma unroll
    for (int i = 0; i < 4; i++)
        #pragma unroll
        for (int j = 0; j < 4; j++)
            #pragma unroll
            for (int h = 0; h < 4; h++) acc[i][j][h] = 0.f;

    int a_r[2], a_c[2], b_r[2], b_c[2];
    #pragma unroll
    for (int i = 0; i < 2; i++) {
        const int idx = tid + (i << 8);
        a_r[i] = idx >> 2;  a_c[i] = (idx & 3) << 2;
        b_r[i] = idx >> 5;  b_c[i] = (idx & 31) << 2;
    }

    float4 pa[2], pb[2];
    #pragma unroll
    for (int i = 0; i < 2; i++) {
        pa[i] = *(const float4*)&A[(size_t)(bm + a_r[i]) * K + a_c[i]];
        pb[i] = *(const float4*)&W[(size_t)b_r[i] * N + bn + b_c[i]];
    }

    const int ntiles = K >> 4;
    for (int kt = 0; kt < ntiles; kt++) {
        #pragma unroll
        for (int i = 0; i < 2; i++) {
            As[a_r[i]][a_c[i] + 0] = f2tf(pa[i].x);
            As[a_r[i]][a_c[i] + 1] = f2tf(pa[i].y);
            As[a_r[i]][a_c[i] + 2] = f2tf(pa[i].z);
            As[a_r[i]][a_c[i] + 3] = f2tf(pa[i].w);
            uint4 bw;
            bw.x = f2tf(pb[i].x); bw.y = f2tf(pb[i].y);
            bw.z = f2tf(pb[i].z); bw.w = f2tf(pb[i].w);
            *(uint4*)&Bs[b_r[i]][b_c[i]] = bw;
        }
        __syncthreads();

        if (kt + 1 < ntiles) {
            const int k0 = (kt + 1) << 4;
            #pragma unroll
            for (int i = 0; i < 2; i++) {
                pa[i] = *(const float4*)&A[(size_t)(bm + a_r[i]) * K + k0 + a_c[i]];
                pb[i] = *(const float4*)&W[(size_t)(k0 + b_r[i]) * N + bn + b_c[i]];
            }
        }

        #pragma unroll
        for (int ks = 0; ks < 2; ks++) {
            const int kb = ks << 3;
            uint32_t af[4][4], bf[4][2];
            #pragma unroll
            for (int mt = 0; mt < 4; mt++) {
                const int m = wm + (mt << 4) + g;
                af[mt][0] = As[m    ][kb + t4];
                af[mt][1] = As[m + 8][kb + t4];
                af[mt][2] = As[m    ][kb + t4 + 4];
                af[mt][3] = As[m + 8][kb + t4 + 4];
            }
            #pragma unroll
            for (int nt = 0; nt < 4; nt++) {
                const int n = wn + (nt << 3) + g;
                bf[nt][0] = Bs[kb + t4    ][n];
                bf[nt][1] = Bs[kb + t4 + 4][n];
            }
            #pragma unroll
            for (int mt = 0; mt < 4; mt++)
                #pragma unroll
                for (int nt = 0; nt < 4; nt++)
                    MMA_TF32(acc[mt][nt], af[mt], bf[nt]);
        }
        __syncthreads();
    }

    // epilogue
    #pragma unroll
    for (int mt = 0; mt < 4; mt++) {
        #pragma unroll
        for (int nt = 0; nt < 4; nt++) {
            const int col = bn + wn + (nt << 3) + (t4 << 1);
            const float b0 = DO_BIAS ? bias[col]     : 0.f;
            const float b1 = DO_BIAS ? bias[col + 1] : 0.f;
            #pragma unroll
            for (int h = 0; h < 2; h++) {
                const int row = bm + wm + (mt << 4) + g + (h << 3);
                float v0 = acc[mt][nt][h * 2 + 0] + b0;
                float v1 = acc[mt][nt][h * 2 + 1] + b1;
                if (DO_GELU) {
                    v0 = 0.5f * v0 * (1.f + erff(v0 * 0.70710678118f));
                    v1 = 0.5f * v1 * (1.f + erff(v1 * 0.70710678118f));
                }
                const size_t off = (size_t)row * N + col;
                if (DO_RES) {
                    const float2 r = *(const float2*)&res[off];
                    v0 += r.x; v1 += r.y;
                }
                *(float2*)&C[off] = make_float2(v0, v1);
            }
        }
    }
}

// ---------------- attention: scores = scale * Q @ K^T -------------------------
__global__ void __launch_bounds__(256) attn_scores_k(const float* __restrict__ QKV,
                                                     float* __restrict__ S) {
    __shared__ float Qs[64][68];
    __shared__ float Ks[64][68];
    const int q0 = blockIdx.x << 6;
    const int k0 = blockIdx.y << 6;
    const int bh = blockIdx.z;
    const int b = bh >> 4, h = bh & 15;
    const int tid = threadIdx.x;
    #pragma unroll
    for (int i = 0; i < 4; i++) {
        const int idx = tid + (i << 8);
        const int row = idx >> 4;
        const int c4 = (idx & 15) << 2;
        const float4 qv = *(const float4*)&QKV[(size_t)(b * TT + q0 + row) * (3 * D) + h * HDIM + c4];
        Qs[c4 + 0][row] = qv.x; Qs[c4 + 1][row] = qv.y;
        Qs[c4 + 2][row] = qv.z; Qs[c4 + 3][row] = qv.w;
        const float4 kv = *(const float4*)&QKV[(size_t)(b * TT + k0 + row) * (3 * D) + D + h * HDIM + c4];
        Ks[c4 + 0][row] = kv.x; Ks[c4 + 1][row] = kv.y;
        Ks[c4 + 2][row] = kv.z; Ks[c4 + 3][row] = kv.w;
    }
    __syncthreads();
    const int tx = tid & 15, ty = tid >> 4;
    float acc[4][4];
    #pragma unroll
    for (int i = 0; i < 4; i++)
        #pragma unroll
        for (int j = 0; j < 4; j++) acc[i][j] = 0.f;
    #pragma unroll 8
    for (int d = 0; d < 64; d++) {
        float a[4], bb[4];
        *(float4*)a  = *(const float4*)&Qs[d][ty << 2];
        *(float4*)bb = *(const float4*)&Ks[d][tx << 2];
        #pragma unroll
        for (int i = 0; i < 4; i++)
            #pragma unroll
            for (int j = 0; j < 4; j++)
                acc[i][j] = fmaf(a[i], bb[j], acc[i][j]);
    }
    #pragma unroll
    for (int i = 0; i < 4; i++) {
        float* srow = &S[((size_t)bh * TT + q0 + (ty << 2) + i) * TT + k0 + (tx << 2)];
        *(float4*)srow = make_float4(acc[i][0] * 0.125f, acc[i][1] * 0.125f,
                                     acc[i][2] * 0.125f, acc[i][3] * 0.125f);
    }
}

// ---------------- softmax ------------------------------------------------------
__global__ void __launch_bounds__(256) softmax_k(float* __restrict__ S) {
    __shared__ float sh[8];
    float* row = S + (size_t)blockIdx.x * TT;
    const int base = threadIdx.x << 2;
    float4 v = *(const float4*)(row + base);
    float m = fmaxf(fmaxf(v.x, v.y), fmaxf(v.z, v.w));
    m = blk_max(m, sh);
    v.x = __expf(v.x - m); v.y = __expf(v.y - m);
    v.z = __expf(v.z - m); v.w = __expf(v.w - m);
    float s = blk_sum(v.x + v.y + v.z + v.w, sh);
    const float inv = 1.f / s;
    v.x *= inv; v.y *= inv; v.z *= inv; v.w *= inv;
    *(float4*)(row + base) = v;
}

// ---------------- attention: Y = P @ V -----------------------------------------
__global__ void __launch_bounds__(256) attn_av_k(const float* __restrict__ S,
                                                 const float* __restrict__ QKV,
                                                 float* __restrict__ Y) {
    __shared__ float Ps[64][68];
    __shared__ float Vs[64][68];
    const int q0 = blockIdx.x << 6;
    const int bh = blockIdx.y;
    const int b = bh >> 4, h = bh & 15;
    const int tid = threadIdx.x;
    const int tx = tid & 15, ty = tid >> 4;
    float acc[4][4];
    #pragma unroll
    for (int i = 0; i < 4; i++)
        #pragma unroll
        for (int j = 0; j < 4; j++) acc[i][j] = 0.f;

    for (int kb = 0; kb < TT; kb += 64) {
        #pragma unroll
        for (int i = 0; i < 4; i++) {
            const int idx = tid + (i << 8);
            const int r = idx >> 4;
            const int c4 = (idx & 15) << 2;
            const float4 pv = *(const float4*)&S[((size_t)bh * TT + q0 + r) * TT + kb + c4];
            Ps[c4 + 0][r] = pv.x; Ps[c4 + 1][r] = pv.y;
            Ps[c4 + 2][r] = pv.z; Ps[c4 + 3][r] = pv.w;
            *(float4*)&Vs[r][c4] =
                *(const float4*)&QKV[(size_t)(b * TT + kb + r) * (3 * D) + 2 * D + h * HDIM + c4];
        }
        __syncthreads();
        #pragma unroll 8
        for (int kk = 0; kk < 64; kk++) {
            float a[4], bb[4];
            *(float4*)a  = *(const float4*)&Ps[kk][ty << 2];
            *(float4*)bb = *(const float4*)&Vs[kk][tx << 2];
            #pragma unroll
            for (int i = 0; i < 4; i++)
                #pragma unroll
                for (int j = 0; j < 4; j++)
                    acc[i][j] = fmaf(a[i], bb[j], acc[i][j]);
        }
        __syncthreads();
    }
    #pragma unroll
    for (int i = 0; i < 4; i++) {
        float* yrow = &Y[(size_t)(b * TT + q0 + (ty << 2) + i) * D + h * HDIM + (tx << 2)];
        *(float4*)yrow = make_float4(acc[i][0], acc[i][1], acc[i][2], acc[i][3]);
    }
}

// ---------------- loss ----------------------------------------------------------
__global__ void __launch_bounds__(256) nll_k(const float* __restrict__ logits,
                                             const int* __restrict__ tgt,
                                             float* __restrict__ nll) {
    __shared__ float sh[8];
    const int r = blockIdx.x;
    const float* row = logits + (size_t)r * VOC;
    float m = -1e30f;
    for (int c = threadIdx.x; c < VOC; c += 256) m = fmaxf(m, row[c]);
    m = blk_max(m, sh);
    float s = 0.f;
    for (int c = threadIdx.x; c < VOC; c += 256) s += __expf(row[c] - m);
    s = blk_sum(s, sh);
    if (threadIdx.x == 0) nll[r] = m + logf(s) - row[tgt[r]];
}

__global__ void __launch_bounds__(256) loss_k(const float* __restrict__ nll,
                                              float* __restrict__ out) {
    __shared__ float sh[8];
    float s = 0.f;
    for (int i = threadIdx.x; i < MM; i += 256) s += nll[i];
    s = blk_sum(s, sh);
    if (threadIdx.x == 0) out[0] = s * (1.f / MM);
}

// ---------------- orchestration --------------------------------------------------
extern "C" void kernel_launch(void* const* d_in, const int* in_sizes, int n_in,
                              void* d_out, int out_size) {
    const int*   idx     = (const int*)  d_in[0];
    const int*   targets = (const int*)  d_in[1];
    const float* tok_emb = (const float*)d_in[2];
    const float* pos_emb = (const float*)d_in[3];
    const float* ln1_s   = (const float*)d_in[4];
    const float* ln1_b   = (const float*)d_in[5];
    const float* qkv_w   = (const float*)d_in[6];
    const float* qkv_b   = (const float*)d_in[7];
    const float* proj_w  = (const float*)d_in[8];
    const float* proj_b  = (const float*)d_in[9];
    const float* ln2_s   = (const float*)d_in[10];
    const float* ln2_b   = (const float*)d_in[11];
    const float* fc1_w   = (const float*)d_in[12];
    const float* fc1_b   = (const float*)d_in[13];
    const float* fc2_w   = (const float*)d_in[14];
    const float* fc2_b   = (const float*)d_in[15];
    const float* lnf_s   = (const float*)d_in[16];
    const float* lnf_b   = (const float*)d_in[17];
    const float* head_w  = (const float*)d_in[18];
    float* out = (float*)d_out;

    float *X, *Hb, *QKV, *S, *Y, *FF, *NLL;
    cudaGetSymbolAddress((void**)&X,   g_X);
    cudaGetSymbolAddress((void**)&Hb,  g_Hb);
    cudaGetSymbolAddress((void**)&QKV, g_QKV);
    cudaGetSymbolAddress((void**)&S,   g_S);
    cudaGetSymbolAddress((void**)&Y,   g_Y);
    cudaGetSymbolAddress((void**)&FF,  g_FF);
    cudaGetSymbolAddress((void**)&NLL, g_NLL);

    embed_k<<<MM, 256>>>(idx, tok_emb, pos_emb, X);

    for (int l = 0; l < NL; l++) {
        ln_k<<<MM, 256>>>(X, ln1_s + (size_t)l * D, ln1_b + (size_t)l * D, Hb);
        gemm_tf32_k<1,0,0><<<dim3(3 * D / 128, MM / 128), 256>>>(
            Hb, qkv_w + (size_t)l * D * 3 * D, qkv_b + (size_t)l * 3 * D,
            nullptr, QKV, MM, 3 * D, D);
        attn_scores_k<<<dim3(TT / 64, TT / 64, BB * NH), 256>>>(QKV, S);
        softmax_k<<<BB * NH * TT, 256>>>(S);
        attn_av_k<<<dim3(TT / 64, BB * NH), 256>>>(S, QKV, Y);
        gemm_tf32_k<1,0,1><<<dim3(D / 128, MM / 128), 256>>>(
            Y, proj_w + (size_t)l * D * D, proj_b + (size_t)l * D,
            X, X, MM, D, D);
        ln_k<<<MM, 256>>>(X, ln2_s + (size_t)l * D, ln2_b + (size_t)l * D, Hb);
        gemm_tf32_k<1,1,0><<<dim3(4 * D / 128, MM / 128), 256>>>(
            Hb, fc1_w + (size_t)l * D * 4 * D, fc1_b + (size_t)l * 4 * D,
            nullptr, FF, MM, 4 * D, D);
        gemm_tf32_k<1,0,1><<<dim3(D / 128, MM / 128), 256>>>(
            FF, fc2_w + (size_t)l * 4 * D * D, fc2_b + (size_t)l * D,
            X, X, MM, D, 4 * D);
    }

    ln_k<<<MM, 256>>>(X, lnf_s, lnf_b, Hb);
    gemm_tf32_k<0,0,0><<<dim3(VOC / 128, MM / 128), 256>>>(
        Hb, head_w, nullptr, nullptr, out, MM, VOC, D);

    nll_k<<<MM, 256>>>(out, targets, NLL);
    loss_k<<<1, 256>>>(NLL, out + (size_t)out_size - 1);
}